// round 2
// baseline (speedup 1.0000x reference)
#include <cuda_runtime.h>
#include <math.h>
#include <cstdint>
#include <cstddef>

// Problem constants (fixed shapes from reference)
#define BQ 2048              // windows
#define NT 49                // tokens per window
#define CD 384               // channels
#define NH 12                // heads
#define HD 32                // head dim
#define MROWS (BQ*NT)        // 100352
#define QKVN (3*CD)          // 1152
#define RPE 512
#define TBL 169              // (2*7-1)^2
#define LOG_MAX_SCALE 4.60517018598809136804f

// Scratch (device globals: allocation-free per harness rules)
__device__ float g_qkv[(size_t)MROWS * QKVN];   // [M, 1152]
__device__ float g_ao[(size_t)MROWS * CD];      // [M, 384] attention output
__device__ float g_tab[TBL * NH];               // cpb table [169, 12]
__device__ float g_bias[NH * NT * NT];          // 16*sigmoid(bias) [h][i][j]

// ---------------------------------------------------------------------------
// CPB MLP: per table entry (169), hidden = relu(t @ w1^T + b1) [512],
// tab[h] = hidden @ w2[h]
// ---------------------------------------------------------------------------
__global__ void cpb_mlp_kernel(const float* __restrict__ w1,
                               const float* __restrict__ b1,
                               const float* __restrict__ w2)
{
    int i2 = blockIdx.x;                 // 0..168
    int a = i2 / 13, bcol = i2 % 13;
    float vy = (float)(a - 6) * (8.0f / 6.0f);
    float vx = (float)(bcol - 6) * (8.0f / 6.0f);
    float t0 = copysignf(log2f(fabsf(vy) + 1.0f) / 3.0f, vy);
    float t1 = copysignf(log2f(fabsf(vx) + 1.0f) / 3.0f, vx);

    __shared__ float hidden[RPE];
    __shared__ float red[4];
    int tid = threadIdx.x;               // 128 threads
    for (int r = tid; r < RPE; r += 128) {
        float hv = t0 * w1[2 * r] + t1 * w1[2 * r + 1] + b1[r];
        hidden[r] = fmaxf(hv, 0.0f);
    }
    __syncthreads();
    for (int h = 0; h < NH; h++) {
        float p = 0.0f;
        for (int r = tid; r < RPE; r += 128) p += hidden[r] * w2[h * RPE + r];
        #pragma unroll
        for (int o = 16; o > 0; o >>= 1) p += __shfl_xor_sync(0xffffffffu, p, o);
        if ((tid & 31) == 0) red[tid >> 5] = p;
        __syncthreads();
        if (tid == 0) g_tab[i2 * NH + h] = red[0] + red[1] + red[2] + red[3];
        __syncthreads();
    }
}

// Expand to [h][i][j] with relative-index gather + 16*sigmoid
__global__ void bias_expand_kernel()
{
    int t = blockIdx.x * 256 + threadIdx.x;
    if (t >= NH * NT * NT) return;
    int h = t / (NT * NT);
    int ij = t % (NT * NT);
    int i = ij / NT, j = ij % NT;
    int rel = ((i / 7 - j / 7) + 6) * 13 + ((i % 7 - j % 7) + 6);
    float x = g_tab[rel * NH + h];
    g_bias[t] = 16.0f / (1.0f + expf(-x));
}

// ---------------------------------------------------------------------------
// SGEMM: C[M,NC] = A[M,K] @ B[NC,K]^T + bias. 128x128 tile, BK=16, 8x8/thread.
// MODE 0: qkv bias (q_bias | 0 | v_bias). MODE 1: plain bias vector.
// Assumes M % 128 == 0, NC % 128 == 0, K % 16 == 0 (true for all uses here).
// ---------------------------------------------------------------------------
template<int NC, int K, int MODE>
__global__ void __launch_bounds__(256) sgemm_nt(
    const float* __restrict__ A, const float* __restrict__ B,
    float* __restrict__ C,
    const float* __restrict__ bias0, const float* __restrict__ bias1)
{
    constexpr int BK = 16;
    __shared__ float As[BK][128];
    __shared__ float Bs[BK][128];

    int tid = threadIdx.x;
    int m0 = blockIdx.y * 128;
    int n0 = blockIdx.x * 128;
    int tx = tid & 15;          // 0..15 -> N strip
    int ty = tid >> 4;          // 0..15 -> M strip
    int lrow = tid >> 2;        // 0..63
    int lcol = (tid & 3) << 2;  // 0,4,8,12

    float acc[8][8];
    #pragma unroll
    for (int i = 0; i < 8; i++)
        #pragma unroll
        for (int j = 0; j < 8; j++) acc[i][j] = 0.0f;

    const float* Abase = A + (size_t)(m0 + lrow) * K + lcol;
    const float* Bbase = B + (size_t)(n0 + lrow) * K + lcol;

    for (int k0 = 0; k0 < K; k0 += BK) {
        float4 a0 = *(const float4*)(Abase + k0);
        float4 a1 = *(const float4*)(Abase + (size_t)64 * K + k0);
        float4 b0 = *(const float4*)(Bbase + k0);
        float4 b1 = *(const float4*)(Bbase + (size_t)64 * K + k0);
        __syncthreads();
        As[lcol + 0][lrow] = a0.x; As[lcol + 1][lrow] = a0.y;
        As[lcol + 2][lrow] = a0.z; As[lcol + 3][lrow] = a0.w;
        As[lcol + 0][lrow + 64] = a1.x; As[lcol + 1][lrow + 64] = a1.y;
        As[lcol + 2][lrow + 64] = a1.z; As[lcol + 3][lrow + 64] = a1.w;
        Bs[lcol + 0][lrow] = b0.x; Bs[lcol + 1][lrow] = b0.y;
        Bs[lcol + 2][lrow] = b0.z; Bs[lcol + 3][lrow] = b0.w;
        Bs[lcol + 0][lrow + 64] = b1.x; Bs[lcol + 1][lrow + 64] = b1.y;
        Bs[lcol + 2][lrow + 64] = b1.z; Bs[lcol + 3][lrow + 64] = b1.w;
        __syncthreads();
        #pragma unroll
        for (int kk = 0; kk < BK; kk++) {
            float ra[8], rb[8];
            *(float4*)(ra)     = *(const float4*)(&As[kk][ty * 8]);
            *(float4*)(ra + 4) = *(const float4*)(&As[kk][ty * 8 + 4]);
            *(float4*)(rb)     = *(const float4*)(&Bs[kk][tx * 8]);
            *(float4*)(rb + 4) = *(const float4*)(&Bs[kk][tx * 8 + 4]);
            #pragma unroll
            for (int i = 0; i < 8; i++)
                #pragma unroll
                for (int j = 0; j < 8; j++)
                    acc[i][j] = fmaf(ra[i], rb[j], acc[i][j]);
        }
    }

    float bv[8];
    #pragma unroll
    for (int j = 0; j < 8; j++) {
        int n = n0 + tx * 8 + j;
        if (MODE == 0)
            bv[j] = (n < CD) ? bias0[n] : ((n < 2 * CD) ? 0.0f : bias1[n - 2 * CD]);
        else
            bv[j] = bias0[n];
    }
    #pragma unroll
    for (int i = 0; i < 8; i++) {
        size_t m = (size_t)(m0 + ty * 8 + i);
        float* crow = C + m * NC + n0 + tx * 8;
        float4 o0 = make_float4(acc[i][0] + bv[0], acc[i][1] + bv[1],
                                acc[i][2] + bv[2], acc[i][3] + bv[3]);
        float4 o1 = make_float4(acc[i][4] + bv[4], acc[i][5] + bv[5],
                                acc[i][6] + bv[6], acc[i][7] + bv[7]);
        *(float4*)(crow) = o0;
        *(float4*)(crow + 4) = o1;
    }
}

// ---------------------------------------------------------------------------
// Attention: one CTA per (window, head). smem q/k/v (pad 33), cosine attn
// with clamped exp scale, + precomputed bias, softmax, P@V.
// ---------------------------------------------------------------------------
__global__ void __launch_bounds__(256) attn_kernel(const float* __restrict__ logit_scale)
{
    int bh = blockIdx.x;
    int b = bh / NH, h = bh % NH;
    __shared__ float qs[NT * 33];
    __shared__ float ks[NT * 33];
    __shared__ float vs[NT * 33];
    __shared__ float ps[NT * 50];

    int tid = threadIdx.x, lane = tid & 31, warp = tid >> 5;
    float scale = expf(fminf(logit_scale[h], LOG_MAX_SCALE));

    size_t base = (size_t)(b * NT) * QKVN + (size_t)h * HD;
    for (int idx = tid; idx < NT * HD; idx += 256) {
        int i = idx >> 5, d = idx & 31;
        size_t off = base + (size_t)i * QKVN + d;
        qs[i * 33 + d] = g_qkv[off];
        ks[i * 33 + d] = g_qkv[off + CD];
        vs[i * 33 + d] = g_qkv[off + 2 * CD];
    }
    const float* bptr = &g_bias[h * NT * NT];
    for (int idx = tid; idx < NT * NT; idx += 256) {
        int i = idx / NT, j = idx % NT;
        ps[i * 50 + j] = bptr[idx];
    }
    __syncthreads();

    // l2-normalize q, k rows (warp-per-row)
    for (int i = warp; i < NT; i += 8) {
        float qv = qs[i * 33 + lane];
        float s = qv * qv;
        #pragma unroll
        for (int o = 16; o > 0; o >>= 1) s += __shfl_xor_sync(0xffffffffu, s, o);
        qs[i * 33 + lane] = qv / (sqrtf(s) + 1e-12f);
        float kv = ks[i * 33 + lane];
        float s2 = kv * kv;
        #pragma unroll
        for (int o = 16; o > 0; o >>= 1) s2 += __shfl_xor_sync(0xffffffffu, s2, o);
        ks[i * 33 + lane] = kv / (sqrtf(s2) + 1e-12f);
    }
    __syncthreads();

    // scores + softmax, row-per-warp; lane covers columns {lane, lane+32}
    for (int i = warp; i < NT; i += 8) {
        const float* q = &qs[i * 33];
        int j1 = (lane < 17) ? (lane + 32) : 0;   // safe index for inactive lanes
        const float* k0 = &ks[lane * 33];
        const float* k1 = &ks[j1 * 33];
        float d0 = 0.0f, d1 = 0.0f;
        #pragma unroll
        for (int kk = 0; kk < HD; kk++) {
            float qv = q[kk];
            d0 = fmaf(qv, k0[kk], d0);
            d1 = fmaf(qv, k1[kk], d1);
        }
        float s0 = d0 * scale + ps[i * 50 + lane];
        float s1 = (lane < 17) ? (d1 * scale + ps[i * 50 + 32 + lane]) : -INFINITY;
        float m = fmaxf(s0, s1);
        #pragma unroll
        for (int o = 16; o > 0; o >>= 1) m = fmaxf(m, __shfl_xor_sync(0xffffffffu, m, o));
        float e0 = expf(s0 - m);
        float e1 = (lane < 17) ? expf(s1 - m) : 0.0f;
        float sum = e0 + e1;
        #pragma unroll
        for (int o = 16; o > 0; o >>= 1) sum += __shfl_xor_sync(0xffffffffu, sum, o);
        float inv = 1.0f / sum;
        ps[i * 50 + lane] = e0 * inv;
        if (lane < 17) ps[i * 50 + 32 + lane] = e1 * inv;
    }
    __syncthreads();

    // O = P @ V, row-per-warp, lane = head-dim index
    for (int i = warp; i < NT; i += 8) {
        float acc = 0.0f;
        #pragma unroll
        for (int j = 0; j < NT; j++)
            acc = fmaf(ps[i * 50 + j], vs[j * 33 + lane], acc);
        g_ao[(size_t)(b * NT + i) * CD + h * HD + lane] = acc;
    }
}

// ---------------------------------------------------------------------------
extern "C" void kernel_launch(void* const* d_in, const int* in_sizes, int n_in,
                              void* d_out, int out_size)
{
    const float* x           = (const float*)d_in[0];
    const float* qkv_w       = (const float*)d_in[1];
    const float* q_bias      = (const float*)d_in[2];
    const float* v_bias      = (const float*)d_in[3];
    const float* logit_scale = (const float*)d_in[4];
    const float* cpb_w1      = (const float*)d_in[5];
    const float* cpb_b1      = (const float*)d_in[6];
    const float* cpb_w2      = (const float*)d_in[7];
    const float* proj_w      = (const float*)d_in[8];
    const float* proj_b      = (const float*)d_in[9];
    float* out = (float*)d_out;

    void* p;
    cudaGetSymbolAddress(&p, g_qkv); float* qkv = (float*)p;
    cudaGetSymbolAddress(&p, g_ao);  float* ao  = (float*)p;

    cpb_mlp_kernel<<<TBL, 128>>>(cpb_w1, cpb_b1, cpb_w2);
    bias_expand_kernel<<<(NH * NT * NT + 255) / 256, 256>>>();

    dim3 gq(QKVN / 128, MROWS / 128);
    sgemm_nt<QKVN, CD, 0><<<gq, 256>>>(x, qkv_w, qkv, q_bias, v_bias);

    attn_kernel<<<BQ * NH, 256>>>(logit_scale);

    dim3 gp(CD / 128, MROWS / 128);
    sgemm_nt<CD, CD, 1><<<gp, 256>>>(ao, proj_w, out, proj_b, nullptr);
}

// round 3
// speedup vs baseline: 1.8579x; 1.8579x over previous
#include <cuda_runtime.h>
#include <math.h>
#include <cstdint>
#include <cstddef>

#define BQ 2048
#define NT 49
#define CD 384
#define NH 12
#define HD 32
#define MROWS (BQ*NT)        // 100352
#define QKVN (3*CD)          // 1152
#define RPE 512
#define TBL 169
#define LOG_MAX_SCALE 4.60517018598809136804f

__device__ float g_qkv[(size_t)MROWS * QKVN];
__device__ float g_ao[(size_t)MROWS * CD];
__device__ float g_tab[TBL * NH];
__device__ float g_bias[NH * NT * NT];

// ---------------------------------------------------------------------------
__global__ void cpb_mlp_kernel(const float* __restrict__ w1,
                               const float* __restrict__ b1,
                               const float* __restrict__ w2)
{
    int i2 = blockIdx.x;
    int a = i2 / 13, bcol = i2 % 13;
    float vy = (float)(a - 6) * (8.0f / 6.0f);
    float vx = (float)(bcol - 6) * (8.0f / 6.0f);
    float t0 = copysignf(log2f(fabsf(vy) + 1.0f) / 3.0f, vy);
    float t1 = copysignf(log2f(fabsf(vx) + 1.0f) / 3.0f, vx);

    __shared__ float hidden[RPE];
    __shared__ float red[4];
    int tid = threadIdx.x;
    for (int r = tid; r < RPE; r += 128) {
        float hv = t0 * w1[2 * r] + t1 * w1[2 * r + 1] + b1[r];
        hidden[r] = fmaxf(hv, 0.0f);
    }
    __syncthreads();
    for (int h = 0; h < NH; h++) {
        float p = 0.0f;
        for (int r = tid; r < RPE; r += 128) p += hidden[r] * w2[h * RPE + r];
        #pragma unroll
        for (int o = 16; o > 0; o >>= 1) p += __shfl_xor_sync(0xffffffffu, p, o);
        if ((tid & 31) == 0) red[tid >> 5] = p;
        __syncthreads();
        if (tid == 0) g_tab[i2 * NH + h] = red[0] + red[1] + red[2] + red[3];
        __syncthreads();
    }
}

__global__ void bias_expand_kernel()
{
    int t = blockIdx.x * 256 + threadIdx.x;
    if (t >= NH * NT * NT) return;
    int h = t / (NT * NT);
    int ij = t % (NT * NT);
    int i = ij / NT, j = ij % NT;
    int rel = ((i / 7 - j / 7) + 6) * 13 + ((i % 7 - j % 7) + 6);
    float x = g_tab[rel * NH + h];
    g_bias[t] = 16.0f / (1.0f + __expf(-x));
}

// ---------------------------------------------------------------------------
// TF32 tensor-core GEMM: C[M,NC] = A[M,K] @ B[NC,K]^T + bias
// 128x128 CTA tile, BK=32, 8 warps, warp tile 32x64 via m16n8k8 tf32 mma.
// MODE 0: qkv split bias (q | 0 | v). MODE 1: plain bias.
// Requires M%128==0, NC%128==0, K%32==0.
// ---------------------------------------------------------------------------
__device__ __forceinline__ uint32_t f2tf32(float f) {
    uint32_t r;
    asm("cvt.rna.tf32.f32 %0, %1;" : "=r"(r) : "f"(f));
    return r;
}

__device__ __forceinline__ void mma1688(float c[4], const uint32_t a[4], const uint32_t b[2]) {
    asm volatile(
        "mma.sync.aligned.m16n8k8.row.col.f32.tf32.tf32.f32 "
        "{%0,%1,%2,%3}, {%4,%5,%6,%7}, {%8,%9}, {%0,%1,%2,%3};"
        : "+f"(c[0]), "+f"(c[1]), "+f"(c[2]), "+f"(c[3])
        : "r"(a[0]), "r"(a[1]), "r"(a[2]), "r"(a[3]), "r"(b[0]), "r"(b[1]));
}

template<int NC, int K, int MODE>
__global__ void __launch_bounds__(256) gemm_tf32(
    const float* __restrict__ A, const float* __restrict__ B,
    float* __restrict__ C,
    const float* __restrict__ bias0, const float* __restrict__ bias1)
{
    constexpr int LDS_ = 36;  // 32 + 4 pad: conflict-free frag loads
    __shared__ uint32_t As[128 * LDS_];
    __shared__ uint32_t Bs[128 * LDS_];

    int tid = threadIdx.x;
    int lane = tid & 31, w = tid >> 5;
    int g = lane >> 2, t4 = lane & 3;
    int warp_m = (w >> 1) * 32;
    int warp_n = (w & 1) * 64;
    int m0 = blockIdx.y * 128;
    int n0 = blockIdx.x * 128;

    int lr = tid >> 3;          // 0..31
    int lc = (tid & 7) * 4;     // 0..28

    const float* Ap = A + (size_t)(m0 + lr) * K + lc;
    const float* Bp = B + (size_t)(n0 + lr) * K + lc;

    float acc[2][8][4];
    #pragma unroll
    for (int mi = 0; mi < 2; mi++)
        #pragma unroll
        for (int ni = 0; ni < 8; ni++)
            #pragma unroll
            for (int q = 0; q < 4; q++) acc[mi][ni][q] = 0.0f;

    float4 ra[4], rb[4];
    #pragma unroll
    for (int p = 0; p < 4; p++) {
        ra[p] = *(const float4*)(Ap + (size_t)(32 * p) * K);
        rb[p] = *(const float4*)(Bp + (size_t)(32 * p) * K);
    }

    for (int k0 = 0; k0 < K; k0 += 32) {
        #pragma unroll
        for (int p = 0; p < 4; p++) {
            int row = lr + 32 * p;
            uint32_t* as = &As[row * LDS_ + lc];
            as[0] = f2tf32(ra[p].x); as[1] = f2tf32(ra[p].y);
            as[2] = f2tf32(ra[p].z); as[3] = f2tf32(ra[p].w);
            uint32_t* bs = &Bs[row * LDS_ + lc];
            bs[0] = f2tf32(rb[p].x); bs[1] = f2tf32(rb[p].y);
            bs[2] = f2tf32(rb[p].z); bs[3] = f2tf32(rb[p].w);
        }
        __syncthreads();

        if (k0 + 32 < K) {
            #pragma unroll
            for (int p = 0; p < 4; p++) {
                ra[p] = *(const float4*)(Ap + (size_t)(32 * p) * K + (k0 + 32));
                rb[p] = *(const float4*)(Bp + (size_t)(32 * p) * K + (k0 + 32));
            }
        }

        #pragma unroll
        for (int kk0 = 0; kk0 < 32; kk0 += 8) {
            uint32_t af[2][4], bf[8][2];
            #pragma unroll
            for (int mi = 0; mi < 2; mi++) {
                int r = warp_m + mi * 16 + g;
                af[mi][0] = As[r * LDS_ + kk0 + t4];
                af[mi][1] = As[(r + 8) * LDS_ + kk0 + t4];
                af[mi][2] = As[r * LDS_ + kk0 + t4 + 4];
                af[mi][3] = As[(r + 8) * LDS_ + kk0 + t4 + 4];
            }
            #pragma unroll
            for (int ni = 0; ni < 8; ni++) {
                int c = warp_n + ni * 8 + g;
                bf[ni][0] = Bs[c * LDS_ + kk0 + t4];
                bf[ni][1] = Bs[c * LDS_ + kk0 + t4 + 4];
            }
            #pragma unroll
            for (int mi = 0; mi < 2; mi++)
                #pragma unroll
                for (int ni = 0; ni < 8; ni++)
                    mma1688(acc[mi][ni], af[mi], bf[ni]);
        }
        __syncthreads();
    }

    // epilogue
    #pragma unroll
    for (int ni = 0; ni < 8; ni++) {
        int col = n0 + warp_n + ni * 8 + 2 * t4;
        float bx, by;
        if (MODE == 0) {
            bx = (col < CD) ? bias0[col] : ((col < 2 * CD) ? 0.0f : bias1[col - 2 * CD]);
            int c1 = col + 1;
            by = (c1 < CD) ? bias0[c1] : ((c1 < 2 * CD) ? 0.0f : bias1[c1 - 2 * CD]);
        } else {
            bx = bias0[col]; by = bias0[col + 1];
        }
        #pragma unroll
        for (int mi = 0; mi < 2; mi++) {
            int row = m0 + warp_m + mi * 16 + g;
            float2 o0 = make_float2(acc[mi][ni][0] + bx, acc[mi][ni][1] + by);
            float2 o1 = make_float2(acc[mi][ni][2] + bx, acc[mi][ni][3] + by);
            *(float2*)(C + (size_t)row * NC + col) = o0;
            *(float2*)(C + (size_t)(row + 8) * NC + col) = o1;
        }
    }
}

// ---------------------------------------------------------------------------
// Attention: one CTA per (window, head). 2 rows per warp per pass to double
// FMA density per shared load.
// ---------------------------------------------------------------------------
__global__ void __launch_bounds__(256) attn_kernel(const float* __restrict__ logit_scale)
{
    int bh = blockIdx.x;
    int b = bh / NH, h = bh % NH;
    __shared__ float qs[NT * 33];
    __shared__ float ks[NT * 33];
    __shared__ float vs[NT * 33];
    __shared__ float ps[NT * 50];

    int tid = threadIdx.x, lane = tid & 31, warp = tid >> 5;
    float scale = __expf(fminf(logit_scale[h], LOG_MAX_SCALE));

    size_t base = (size_t)(b * NT) * QKVN + (size_t)h * HD;
    for (int idx = tid; idx < NT * HD; idx += 256) {
        int i = idx >> 5, d = idx & 31;
        size_t off = base + (size_t)i * QKVN + d;
        qs[i * 33 + d] = g_qkv[off];
        ks[i * 33 + d] = g_qkv[off + CD];
        vs[i * 33 + d] = g_qkv[off + 2 * CD];
    }
    const float* bptr = &g_bias[h * NT * NT];
    for (int idx = tid; idx < NT * NT; idx += 256) {
        int i = idx / NT, j = idx % NT;
        ps[i * 50 + j] = bptr[idx];
    }
    __syncthreads();

    // l2 normalize q and k rows
    for (int i = warp; i < NT; i += 8) {
        float qv = qs[i * 33 + lane];
        float s = qv * qv;
        #pragma unroll
        for (int o = 16; o > 0; o >>= 1) s += __shfl_xor_sync(0xffffffffu, s, o);
        qs[i * 33 + lane] = qv / (sqrtf(s) + 1e-12f);
        float kv = ks[i * 33 + lane];
        float s2 = kv * kv;
        #pragma unroll
        for (int o = 16; o > 0; o >>= 1) s2 += __shfl_xor_sync(0xffffffffu, s2, o);
        ks[i * 33 + lane] = kv / (sqrtf(s2) + 1e-12f);
    }
    __syncthreads();

    // scores + softmax: 2 rows per warp per pass, lane covers cols {lane, lane+32}
    int j1 = (lane < 17) ? (lane + 32) : 0;
    const float* k0p = &ks[lane * 33];
    const float* k1p = &ks[j1 * 33];
    for (int i0 = warp * 2; i0 < NT; i0 += 16) {
        int i1r = (i0 + 1 < NT) ? (i0 + 1) : i0;
        bool has1 = (i0 + 1 < NT);
        const float* q0 = &qs[i0 * 33];
        const float* q1 = &qs[i1r * 33];
        float d00 = 0.f, d01 = 0.f, d10 = 0.f, d11 = 0.f;
        #pragma unroll
        for (int kk = 0; kk < HD; kk++) {
            float kv0 = k0p[kk], kv1 = k1p[kk];
            float qv0 = q0[kk], qv1 = q1[kk];
            d00 = fmaf(qv0, kv0, d00); d01 = fmaf(qv0, kv1, d01);
            d10 = fmaf(qv1, kv0, d10); d11 = fmaf(qv1, kv1, d11);
        }
        // row i0
        {
            float s0 = d00 * scale + ps[i0 * 50 + lane];
            float s1 = (lane < 17) ? (d01 * scale + ps[i0 * 50 + 32 + lane]) : -INFINITY;
            float m = fmaxf(s0, s1);
            #pragma unroll
            for (int o = 16; o > 0; o >>= 1) m = fmaxf(m, __shfl_xor_sync(0xffffffffu, m, o));
            float e0 = __expf(s0 - m);
            float e1 = (lane < 17) ? __expf(s1 - m) : 0.0f;
            float sum = e0 + e1;
            #pragma unroll
            for (int o = 16; o > 0; o >>= 1) sum += __shfl_xor_sync(0xffffffffu, sum, o);
            float inv = __fdividef(1.0f, sum);
            ps[i0 * 50 + lane] = e0 * inv;
            if (lane < 17) ps[i0 * 50 + 32 + lane] = e1 * inv;
        }
        // row i1
        if (has1) {
            int i1 = i0 + 1;
            float s0 = d10 * scale + ps[i1 * 50 + lane];
            float s1 = (lane < 17) ? (d11 * scale + ps[i1 * 50 + 32 + lane]) : -INFINITY;
            float m = fmaxf(s0, s1);
            #pragma unroll
            for (int o = 16; o > 0; o >>= 1) m = fmaxf(m, __shfl_xor_sync(0xffffffffu, m, o));
            float e0 = __expf(s0 - m);
            float e1 = (lane < 17) ? __expf(s1 - m) : 0.0f;
            float sum = e0 + e1;
            #pragma unroll
            for (int o = 16; o > 0; o >>= 1) sum += __shfl_xor_sync(0xffffffffu, sum, o);
            float inv = __fdividef(1.0f, sum);
            ps[i1 * 50 + lane] = e0 * inv;
            if (lane < 17) ps[i1 * 50 + 32 + lane] = e1 * inv;
        }
    }
    __syncthreads();

    // O = P @ V: 2 rows per warp per pass, lane = head dim
    for (int i0 = warp * 2; i0 < NT; i0 += 16) {
        bool has1 = (i0 + 1 < NT);
        int i1 = has1 ? (i0 + 1) : i0;
        float a0 = 0.f, a1 = 0.f;
        const float* p0 = &ps[i0 * 50];
        const float* p1 = &ps[i1 * 50];
        #pragma unroll
        for (int j = 0; j < NT; j++) {
            float v = vs[j * 33 + lane];
            a0 = fmaf(p0[j], v, a0);
            a1 = fmaf(p1[j], v, a1);
        }
        g_ao[(size_t)(b * NT + i0) * CD + h * HD + lane] = a0;
        if (has1)
            g_ao[(size_t)(b * NT + i1) * CD + h * HD + lane] = a1;
    }
}

// ---------------------------------------------------------------------------
extern "C" void kernel_launch(void* const* d_in, const int* in_sizes, int n_in,
                              void* d_out, int out_size)
{
    const float* x           = (const float*)d_in[0];
    const float* qkv_w       = (const float*)d_in[1];
    const float* q_bias      = (const float*)d_in[2];
    const float* v_bias      = (const float*)d_in[3];
    const float* logit_scale = (const float*)d_in[4];
    const float* cpb_w1      = (const float*)d_in[5];
    const float* cpb_b1      = (const float*)d_in[6];
    const float* cpb_w2      = (const float*)d_in[7];
    const float* proj_w      = (const float*)d_in[8];
    const float* proj_b      = (const float*)d_in[9];
    float* out = (float*)d_out;

    void* p;
    cudaGetSymbolAddress(&p, g_qkv); float* qkv = (float*)p;
    cudaGetSymbolAddress(&p, g_ao);  float* ao  = (float*)p;

    cpb_mlp_kernel<<<TBL, 128>>>(cpb_w1, cpb_b1, cpb_w2);
    bias_expand_kernel<<<(NH * NT * NT + 255) / 256, 256>>>();

    dim3 gq(QKVN / 128, MROWS / 128);
    gemm_tf32<QKVN, CD, 0><<<gq, 256>>>(x, qkv_w, qkv, q_bias, v_bias);

    attn_kernel<<<BQ * NH, 256>>>(logit_scale);

    dim3 gp(CD / 128, MROWS / 128);
    gemm_tf32<CD, CD, 1><<<gp, 256>>>(ao, proj_w, out, proj_b, nullptr);
}

// round 4
// speedup vs baseline: 2.2199x; 1.1949x over previous
#include <cuda_runtime.h>
#include <math.h>
#include <cstdint>
#include <cstddef>

#define BQ 2048
#define NT 49
#define CD 384
#define NH 12
#define HD 32
#define MROWS (BQ*NT)        // 100352
#define QKVN (3*CD)          // 1152
#define RPE 512
#define TBL 169
#define LOG_MAX_SCALE 4.60517018598809136804f

__device__ float g_qkv[(size_t)MROWS * QKVN];
__device__ float g_ao[(size_t)MROWS * CD];
__device__ float g_tab[TBL * NH];
__device__ float g_bias[NH * NT * NT];

// ---------------------------------------------------------------------------
__global__ void cpb_mlp_kernel(const float* __restrict__ w1,
                               const float* __restrict__ b1,
                               const float* __restrict__ w2)
{
    int i2 = blockIdx.x;
    int a = i2 / 13, bcol = i2 % 13;
    float vy = (float)(a - 6) * (8.0f / 6.0f);
    float vx = (float)(bcol - 6) * (8.0f / 6.0f);
    float t0 = copysignf(log2f(fabsf(vy) + 1.0f) / 3.0f, vy);
    float t1 = copysignf(log2f(fabsf(vx) + 1.0f) / 3.0f, vx);

    __shared__ float hidden[RPE];
    __shared__ float red[4];
    int tid = threadIdx.x;
    for (int r = tid; r < RPE; r += 128) {
        float hv = t0 * w1[2 * r] + t1 * w1[2 * r + 1] + b1[r];
        hidden[r] = fmaxf(hv, 0.0f);
    }
    __syncthreads();
    for (int h = 0; h < NH; h++) {
        float p = 0.0f;
        for (int r = tid; r < RPE; r += 128) p += hidden[r] * w2[h * RPE + r];
        #pragma unroll
        for (int o = 16; o > 0; o >>= 1) p += __shfl_xor_sync(0xffffffffu, p, o);
        if ((tid & 31) == 0) red[tid >> 5] = p;
        __syncthreads();
        if (tid == 0) g_tab[i2 * NH + h] = red[0] + red[1] + red[2] + red[3];
        __syncthreads();
    }
}

__global__ void bias_expand_kernel()
{
    int t = blockIdx.x * 256 + threadIdx.x;
    if (t >= NH * NT * NT) return;
    int h = t / (NT * NT);
    int ij = t % (NT * NT);
    int i = ij / NT, j = ij % NT;
    int rel = ((i / 7 - j / 7) + 6) * 13 + ((i % 7 - j % 7) + 6);
    float x = g_tab[rel * NH + h];
    g_bias[t] = 16.0f / (1.0f + __expf(-x));
}

// ---------------------------------------------------------------------------
// TF32 tensor-core GEMM (unchanged from round 3)
// ---------------------------------------------------------------------------
__device__ __forceinline__ uint32_t f2tf32(float f) {
    uint32_t r;
    asm("cvt.rna.tf32.f32 %0, %1;" : "=r"(r) : "f"(f));
    return r;
}

__device__ __forceinline__ void mma1688(float c[4], const uint32_t a[4], const uint32_t b[2]) {
    asm volatile(
        "mma.sync.aligned.m16n8k8.row.col.f32.tf32.tf32.f32 "
        "{%0,%1,%2,%3}, {%4,%5,%6,%7}, {%8,%9}, {%0,%1,%2,%3};"
        : "+f"(c[0]), "+f"(c[1]), "+f"(c[2]), "+f"(c[3])
        : "r"(a[0]), "r"(a[1]), "r"(a[2]), "r"(a[3]), "r"(b[0]), "r"(b[1]));
}

template<int NC, int K, int MODE>
__global__ void __launch_bounds__(256) gemm_tf32(
    const float* __restrict__ A, const float* __restrict__ B,
    float* __restrict__ C,
    const float* __restrict__ bias0, const float* __restrict__ bias1)
{
    constexpr int LDS_ = 36;
    __shared__ uint32_t As[128 * LDS_];
    __shared__ uint32_t Bs[128 * LDS_];

    int tid = threadIdx.x;
    int lane = tid & 31, w = tid >> 5;
    int g = lane >> 2, t4 = lane & 3;
    int warp_m = (w >> 1) * 32;
    int warp_n = (w & 1) * 64;
    int m0 = blockIdx.y * 128;
    int n0 = blockIdx.x * 128;

    int lr = tid >> 3;
    int lc = (tid & 7) * 4;

    const float* Ap = A + (size_t)(m0 + lr) * K + lc;
    const float* Bp = B + (size_t)(n0 + lr) * K + lc;

    float acc[2][8][4];
    #pragma unroll
    for (int mi = 0; mi < 2; mi++)
        #pragma unroll
        for (int ni = 0; ni < 8; ni++)
            #pragma unroll
            for (int q = 0; q < 4; q++) acc[mi][ni][q] = 0.0f;

    float4 ra[4], rb[4];
    #pragma unroll
    for (int p = 0; p < 4; p++) {
        ra[p] = *(const float4*)(Ap + (size_t)(32 * p) * K);
        rb[p] = *(const float4*)(Bp + (size_t)(32 * p) * K);
    }

    for (int k0 = 0; k0 < K; k0 += 32) {
        #pragma unroll
        for (int p = 0; p < 4; p++) {
            int row = lr + 32 * p;
            uint32_t* as = &As[row * LDS_ + lc];
            as[0] = f2tf32(ra[p].x); as[1] = f2tf32(ra[p].y);
            as[2] = f2tf32(ra[p].z); as[3] = f2tf32(ra[p].w);
            uint32_t* bs = &Bs[row * LDS_ + lc];
            bs[0] = f2tf32(rb[p].x); bs[1] = f2tf32(rb[p].y);
            bs[2] = f2tf32(rb[p].z); bs[3] = f2tf32(rb[p].w);
        }
        __syncthreads();

        if (k0 + 32 < K) {
            #pragma unroll
            for (int p = 0; p < 4; p++) {
                ra[p] = *(const float4*)(Ap + (size_t)(32 * p) * K + (k0 + 32));
                rb[p] = *(const float4*)(Bp + (size_t)(32 * p) * K + (k0 + 32));
            }
        }

        #pragma unroll
        for (int kk0 = 0; kk0 < 32; kk0 += 8) {
            uint32_t af[2][4], bf[8][2];
            #pragma unroll
            for (int mi = 0; mi < 2; mi++) {
                int r = warp_m + mi * 16 + g;
                af[mi][0] = As[r * LDS_ + kk0 + t4];
                af[mi][1] = As[(r + 8) * LDS_ + kk0 + t4];
                af[mi][2] = As[r * LDS_ + kk0 + t4 + 4];
                af[mi][3] = As[(r + 8) * LDS_ + kk0 + t4 + 4];
            }
            #pragma unroll
            for (int ni = 0; ni < 8; ni++) {
                int c = warp_n + ni * 8 + g;
                bf[ni][0] = Bs[c * LDS_ + kk0 + t4];
                bf[ni][1] = Bs[c * LDS_ + kk0 + t4 + 4];
            }
            #pragma unroll
            for (int mi = 0; mi < 2; mi++)
                #pragma unroll
                for (int ni = 0; ni < 8; ni++)
                    mma1688(acc[mi][ni], af[mi], bf[ni]);
        }
        __syncthreads();
    }

    #pragma unroll
    for (int ni = 0; ni < 8; ni++) {
        int col = n0 + warp_n + ni * 8 + 2 * t4;
        float bx, by;
        if (MODE == 0) {
            bx = (col < CD) ? bias0[col] : ((col < 2 * CD) ? 0.0f : bias1[col - 2 * CD]);
            int c1 = col + 1;
            by = (c1 < CD) ? bias0[c1] : ((c1 < 2 * CD) ? 0.0f : bias1[c1 - 2 * CD]);
        } else {
            bx = bias0[col]; by = bias0[col + 1];
        }
        #pragma unroll
        for (int mi = 0; mi < 2; mi++) {
            int row = m0 + warp_m + mi * 16 + g;
            float2 o0 = make_float2(acc[mi][ni][0] + bx, acc[mi][ni][1] + by);
            float2 o1 = make_float2(acc[mi][ni][2] + bx, acc[mi][ni][3] + by);
            *(float2*)(C + (size_t)row * NC + col) = o0;
            *(float2*)(C + (size_t)(row + 8) * NC + col) = o1;
        }
    }
}

// ---------------------------------------------------------------------------
// Attention: one CTA per (window, head). All smem traffic vectorized LDS.128,
// V stored transposed, scale folded into normalized q, 4 CTAs/SM target.
// ---------------------------------------------------------------------------
#define QKP 36   // q/k row stride (floats) — float4 aligned, conflict-free
#define PSP 52   // P row stride / Vt row stride

__global__ void __launch_bounds__(256, 4) attn_kernel(const float* __restrict__ logit_scale)
{
    int bh = blockIdx.x;
    int b = bh / NH, h = bh % NH;
    __shared__ float qs[NT * QKP];
    __shared__ float ks[NT * QKP];
    __shared__ float vt[HD * PSP];       // transposed V: vt[d][j]
    __shared__ float ps[NT * PSP];

    int tid = threadIdx.x, lane = tid & 31, warp = tid >> 5;
    float scale = __expf(fminf(logit_scale[h], LOG_MAX_SCALE));

    // load q/k as float4 rows, v transposed
    size_t base = (size_t)(b * NT) * QKVN + (size_t)h * HD;
    for (int idx = tid; idx < NT * 8; idx += 256) {
        int i = idx >> 3, d4 = (idx & 7) * 4;
        size_t off = base + (size_t)i * QKVN + d4;
        float4 qv = *(const float4*)(g_qkv + off);
        float4 kv = *(const float4*)(g_qkv + off + CD);
        float4 vv = *(const float4*)(g_qkv + off + 2 * CD);
        *(float4*)(qs + i * QKP + d4) = qv;
        *(float4*)(ks + i * QKP + d4) = kv;
        vt[(d4 + 0) * PSP + i] = vv.x;
        vt[(d4 + 1) * PSP + i] = vv.y;
        vt[(d4 + 2) * PSP + i] = vv.z;
        vt[(d4 + 3) * PSP + i] = vv.w;
    }
    const float* bptr = &g_bias[h * NT * NT];
    for (int idx = tid; idx < NT * NT; idx += 256) {
        int i = idx / NT, j = idx % NT;
        ps[i * PSP + j] = bptr[idx];
    }
    __syncthreads();

    // l2-normalize q (fold scale), k
    for (int i = warp; i < NT; i += 8) {
        float qv = qs[i * QKP + lane];
        float s = qv * qv;
        #pragma unroll
        for (int o = 16; o > 0; o >>= 1) s += __shfl_xor_sync(0xffffffffu, s, o);
        qs[i * QKP + lane] = qv * (scale / (sqrtf(s) + 1e-12f));
        float kv = ks[i * QKP + lane];
        float s2 = kv * kv;
        #pragma unroll
        for (int o = 16; o > 0; o >>= 1) s2 += __shfl_xor_sync(0xffffffffu, s2, o);
        ks[i * QKP + lane] = kv / (sqrtf(s2) + 1e-12f);
    }
    __syncthreads();

    // scores + softmax: 2 rows/warp, lane covers cols {lane, lane+32}
    int j1 = (lane < 17) ? (lane + 32) : 0;
    for (int i0 = warp * 2; i0 < NT; i0 += 16) {
        bool has1 = (i0 + 1 < NT);
        int i1 = has1 ? (i0 + 1) : i0;
        float d00 = 0.f, d01 = 0.f, d10 = 0.f, d11 = 0.f;
        #pragma unroll
        for (int kk = 0; kk < HD; kk += 4) {
            float4 q0 = *(const float4*)(qs + i0 * QKP + kk);
            float4 q1 = *(const float4*)(qs + i1 * QKP + kk);
            float4 k0 = *(const float4*)(ks + lane * QKP + kk);
            float4 k1 = *(const float4*)(ks + j1 * QKP + kk);
            d00 = fmaf(q0.x, k0.x, d00); d00 = fmaf(q0.y, k0.y, d00);
            d00 = fmaf(q0.z, k0.z, d00); d00 = fmaf(q0.w, k0.w, d00);
            d01 = fmaf(q0.x, k1.x, d01); d01 = fmaf(q0.y, k1.y, d01);
            d01 = fmaf(q0.z, k1.z, d01); d01 = fmaf(q0.w, k1.w, d01);
            d10 = fmaf(q1.x, k0.x, d10); d10 = fmaf(q1.y, k0.y, d10);
            d10 = fmaf(q1.z, k0.z, d10); d10 = fmaf(q1.w, k0.w, d10);
            d11 = fmaf(q1.x, k1.x, d11); d11 = fmaf(q1.y, k1.y, d11);
            d11 = fmaf(q1.z, k1.z, d11); d11 = fmaf(q1.w, k1.w, d11);
        }
        // softmax row i0
        {
            float s0 = d00 + ps[i0 * PSP + lane];
            float s1 = (lane < 17) ? (d01 + ps[i0 * PSP + 32 + lane]) : -INFINITY;
            float m = fmaxf(s0, s1);
            #pragma unroll
            for (int o = 16; o > 0; o >>= 1) m = fmaxf(m, __shfl_xor_sync(0xffffffffu, m, o));
            float e0 = __expf(s0 - m);
            float e1 = (lane < 17) ? __expf(s1 - m) : 0.0f;
            float sum = e0 + e1;
            #pragma unroll
            for (int o = 16; o > 0; o >>= 1) sum += __shfl_xor_sync(0xffffffffu, sum, o);
            float inv = __fdividef(1.0f, sum);
            ps[i0 * PSP + lane] = e0 * inv;
            if (lane < 17) ps[i0 * PSP + 32 + lane] = e1 * inv;
        }
        // softmax row i1
        if (has1) {
            float s0 = d10 + ps[i1 * PSP + lane];
            float s1 = (lane < 17) ? (d11 + ps[i1 * PSP + 32 + lane]) : -INFINITY;
            float m = fmaxf(s0, s1);
            #pragma unroll
            for (int o = 16; o > 0; o >>= 1) m = fmaxf(m, __shfl_xor_sync(0xffffffffu, m, o));
            float e0 = __expf(s0 - m);
            float e1 = (lane < 17) ? __expf(s1 - m) : 0.0f;
            float sum = e0 + e1;
            #pragma unroll
            for (int o = 16; o > 0; o >>= 1) sum += __shfl_xor_sync(0xffffffffu, sum, o);
            float inv = __fdividef(1.0f, sum);
            ps[i1 * PSP + lane] = e0 * inv;
            if (lane < 17) ps[i1 * PSP + 32 + lane] = e1 * inv;
        }
    }
    __syncthreads();

    // O = P @ V via transposed V: lane = head-dim, 2 rows/warp, float4 over j
    for (int i0 = warp * 2; i0 < NT; i0 += 16) {
        bool has1 = (i0 + 1 < NT);
        int i1 = has1 ? (i0 + 1) : i0;
        float a0 = 0.f, a1 = 0.f;
        #pragma unroll
        for (int j = 0; j < 48; j += 4) {
            float4 p0 = *(const float4*)(ps + i0 * PSP + j);
            float4 p1 = *(const float4*)(ps + i1 * PSP + j);
            float4 vv = *(const float4*)(vt + lane * PSP + j);
            a0 = fmaf(p0.x, vv.x, a0); a0 = fmaf(p0.y, vv.y, a0);
            a0 = fmaf(p0.z, vv.z, a0); a0 = fmaf(p0.w, vv.w, a0);
            a1 = fmaf(p1.x, vv.x, a1); a1 = fmaf(p1.y, vv.y, a1);
            a1 = fmaf(p1.z, vv.z, a1); a1 = fmaf(p1.w, vv.w, a1);
        }
        // tail j=48
        {
            float vv = vt[lane * PSP + 48];
            a0 = fmaf(ps[i0 * PSP + 48], vv, a0);
            a1 = fmaf(ps[i1 * PSP + 48], vv, a1);
        }
        g_ao[(size_t)(b * NT + i0) * CD + h * HD + lane] = a0;
        if (has1)
            g_ao[(size_t)(b * NT + i1) * CD + h * HD + lane] = a1;
    }
}

// ---------------------------------------------------------------------------
extern "C" void kernel_launch(void* const* d_in, const int* in_sizes, int n_in,
                              void* d_out, int out_size)
{
    const float* x           = (const float*)d_in[0];
    const float* qkv_w       = (const float*)d_in[1];
    const float* q_bias      = (const float*)d_in[2];
    const float* v_bias      = (const float*)d_in[3];
    const float* logit_scale = (const float*)d_in[4];
    const float* cpb_w1      = (const float*)d_in[5];
    const float* cpb_b1      = (const float*)d_in[6];
    const float* cpb_w2      = (const float*)d_in[7];
    const float* proj_w      = (const float*)d_in[8];
    const float* proj_b      = (const float*)d_in[9];
    float* out = (float*)d_out;

    void* p;
    cudaGetSymbolAddress(&p, g_qkv); float* qkv = (float*)p;
    cudaGetSymbolAddress(&p, g_ao);  float* ao  = (float*)p;

    cpb_mlp_kernel<<<TBL, 128>>>(cpb_w1, cpb_b1, cpb_w2);
    bias_expand_kernel<<<(NH * NT * NT + 255) / 256, 256>>>();

    dim3 gq(QKVN / 128, MROWS / 128);
    gemm_tf32<QKVN, CD, 0><<<gq, 256>>>(x, qkv_w, qkv, q_bias, v_bias);

    attn_kernel<<<BQ * NH, 256>>>(logit_scale);

    dim3 gp(CD / 128, MROWS / 128);
    gemm_tf32<CD, CD, 1><<<gp, 256>>>(ao, proj_w, out, proj_b, nullptr);
}

// round 5
// speedup vs baseline: 2.7099x; 1.2208x over previous
#include <cuda_runtime.h>
#include <math.h>
#include <cstdint>
#include <cstddef>

#define BQ 2048
#define NT 49
#define CD 384
#define NH 12
#define HD 32
#define MROWS (BQ*NT)        // 100352
#define QKVN (3*CD)          // 1152
#define RPE 512
#define TBL 169
#define LOG_MAX_SCALE 4.60517018598809136804f

__device__ float g_qkv[(size_t)MROWS * QKVN];
__device__ float g_ao[(size_t)MROWS * CD];
__device__ float g_tab[TBL * NH];
__device__ float g_bias[NH * NT * NT];

// ---------------------------------------------------------------------------
__global__ void cpb_mlp_kernel(const float* __restrict__ w1,
                               const float* __restrict__ b1,
                               const float* __restrict__ w2)
{
    int i2 = blockIdx.x;
    int a = i2 / 13, bcol = i2 % 13;
    float vy = (float)(a - 6) * (8.0f / 6.0f);
    float vx = (float)(bcol - 6) * (8.0f / 6.0f);
    float t0 = copysignf(log2f(fabsf(vy) + 1.0f) / 3.0f, vy);
    float t1 = copysignf(log2f(fabsf(vx) + 1.0f) / 3.0f, vx);

    __shared__ float hidden[RPE];
    __shared__ float red[4];
    int tid = threadIdx.x;
    for (int r = tid; r < RPE; r += 128) {
        float hv = t0 * w1[2 * r] + t1 * w1[2 * r + 1] + b1[r];
        hidden[r] = fmaxf(hv, 0.0f);
    }
    __syncthreads();
    for (int h = 0; h < NH; h++) {
        float p = 0.0f;
        for (int r = tid; r < RPE; r += 128) p += hidden[r] * w2[h * RPE + r];
        #pragma unroll
        for (int o = 16; o > 0; o >>= 1) p += __shfl_xor_sync(0xffffffffu, p, o);
        if ((tid & 31) == 0) red[tid >> 5] = p;
        __syncthreads();
        if (tid == 0) g_tab[i2 * NH + h] = red[0] + red[1] + red[2] + red[3];
        __syncthreads();
    }
}

__global__ void bias_expand_kernel()
{
    int t = blockIdx.x * 256 + threadIdx.x;
    if (t >= NH * NT * NT) return;
    int h = t / (NT * NT);
    int ij = t % (NT * NT);
    int i = ij / NT, j = ij % NT;
    int rel = ((i / 7 - j / 7) + 6) * 13 + ((i % 7 - j % 7) + 6);
    float x = g_tab[rel * NH + h];
    g_bias[t] = 16.0f / (1.0f + __expf(-x));
}

// ---------------------------------------------------------------------------
// TF32 tensor-core GEMM (unchanged)
// ---------------------------------------------------------------------------
__device__ __forceinline__ uint32_t f2tf32(float f) {
    uint32_t r;
    asm("cvt.rna.tf32.f32 %0, %1;" : "=r"(r) : "f"(f));
    return r;
}

__device__ __forceinline__ void mma1688(float c[4], const uint32_t a[4], const uint32_t b[2]) {
    asm volatile(
        "mma.sync.aligned.m16n8k8.row.col.f32.tf32.tf32.f32 "
        "{%0,%1,%2,%3}, {%4,%5,%6,%7}, {%8,%9}, {%0,%1,%2,%3};"
        : "+f"(c[0]), "+f"(c[1]), "+f"(c[2]), "+f"(c[3])
        : "r"(a[0]), "r"(a[1]), "r"(a[2]), "r"(a[3]), "r"(b[0]), "r"(b[1]));
}

template<int NC, int K, int MODE>
__global__ void __launch_bounds__(256) gemm_tf32(
    const float* __restrict__ A, const float* __restrict__ B,
    float* __restrict__ C,
    const float* __restrict__ bias0, const float* __restrict__ bias1)
{
    constexpr int LDS_ = 36;
    __shared__ uint32_t As[128 * LDS_];
    __shared__ uint32_t Bs[128 * LDS_];

    int tid = threadIdx.x;
    int lane = tid & 31, w = tid >> 5;
    int g = lane >> 2, t4 = lane & 3;
    int warp_m = (w >> 1) * 32;
    int warp_n = (w & 1) * 64;
    int m0 = blockIdx.y * 128;
    int n0 = blockIdx.x * 128;

    int lr = tid >> 3;
    int lc = (tid & 7) * 4;

    const float* Ap = A + (size_t)(m0 + lr) * K + lc;
    const float* Bp = B + (size_t)(n0 + lr) * K + lc;

    float acc[2][8][4];
    #pragma unroll
    for (int mi = 0; mi < 2; mi++)
        #pragma unroll
        for (int ni = 0; ni < 8; ni++)
            #pragma unroll
            for (int q = 0; q < 4; q++) acc[mi][ni][q] = 0.0f;

    float4 ra[4], rb[4];
    #pragma unroll
    for (int p = 0; p < 4; p++) {
        ra[p] = *(const float4*)(Ap + (size_t)(32 * p) * K);
        rb[p] = *(const float4*)(Bp + (size_t)(32 * p) * K);
    }

    for (int k0 = 0; k0 < K; k0 += 32) {
        #pragma unroll
        for (int p = 0; p < 4; p++) {
            int row = lr + 32 * p;
            uint32_t* as = &As[row * LDS_ + lc];
            as[0] = f2tf32(ra[p].x); as[1] = f2tf32(ra[p].y);
            as[2] = f2tf32(ra[p].z); as[3] = f2tf32(ra[p].w);
            uint32_t* bs = &Bs[row * LDS_ + lc];
            bs[0] = f2tf32(rb[p].x); bs[1] = f2tf32(rb[p].y);
            bs[2] = f2tf32(rb[p].z); bs[3] = f2tf32(rb[p].w);
        }
        __syncthreads();

        if (k0 + 32 < K) {
            #pragma unroll
            for (int p = 0; p < 4; p++) {
                ra[p] = *(const float4*)(Ap + (size_t)(32 * p) * K + (k0 + 32));
                rb[p] = *(const float4*)(Bp + (size_t)(32 * p) * K + (k0 + 32));
            }
        }

        #pragma unroll
        for (int kk0 = 0; kk0 < 32; kk0 += 8) {
            uint32_t af[2][4], bf[8][2];
            #pragma unroll
            for (int mi = 0; mi < 2; mi++) {
                int r = warp_m + mi * 16 + g;
                af[mi][0] = As[r * LDS_ + kk0 + t4];
                af[mi][1] = As[(r + 8) * LDS_ + kk0 + t4];
                af[mi][2] = As[r * LDS_ + kk0 + t4 + 4];
                af[mi][3] = As[(r + 8) * LDS_ + kk0 + t4 + 4];
            }
            #pragma unroll
            for (int ni = 0; ni < 8; ni++) {
                int c = warp_n + ni * 8 + g;
                bf[ni][0] = Bs[c * LDS_ + kk0 + t4];
                bf[ni][1] = Bs[c * LDS_ + kk0 + t4 + 4];
            }
            #pragma unroll
            for (int mi = 0; mi < 2; mi++)
                #pragma unroll
                for (int ni = 0; ni < 8; ni++)
                    mma1688(acc[mi][ni], af[mi], bf[ni]);
        }
        __syncthreads();
    }

    #pragma unroll
    for (int ni = 0; ni < 8; ni++) {
        int col = n0 + warp_n + ni * 8 + 2 * t4;
        float bx, by;
        if (MODE == 0) {
            bx = (col < CD) ? bias0[col] : ((col < 2 * CD) ? 0.0f : bias1[col - 2 * CD]);
            int c1 = col + 1;
            by = (c1 < CD) ? bias0[c1] : ((c1 < 2 * CD) ? 0.0f : bias1[c1 - 2 * CD]);
        } else {
            bx = bias0[col]; by = bias0[col + 1];
        }
        #pragma unroll
        for (int mi = 0; mi < 2; mi++) {
            int row = m0 + warp_m + mi * 16 + g;
            float2 o0 = make_float2(acc[mi][ni][0] + bx, acc[mi][ni][1] + by);
            float2 o1 = make_float2(acc[mi][ni][2] + bx, acc[mi][ni][3] + by);
            *(float2*)(C + (size_t)row * NC + col) = o0;
            *(float2*)(C + (size_t)(row + 8) * NC + col) = o1;
        }
    }
}

// ---------------------------------------------------------------------------
// Attention with register-blocked score & PV phases.
// Each warp owns 4 row-pairs; K-columns and V-chunks are cached in registers
// and reused across all 4 pairs → ~4x fewer smem reads of K and V.
// ---------------------------------------------------------------------------
#define QKP 36   // q/k row stride (floats)
#define PSP 52   // P row stride / Vt row stride

__device__ __forceinline__ float dot4(float4 a, float4 b, float acc) {
    acc = fmaf(a.x, b.x, acc); acc = fmaf(a.y, b.y, acc);
    acc = fmaf(a.z, b.z, acc); acc = fmaf(a.w, b.w, acc);
    return acc;
}

__global__ void __launch_bounds__(256, 4) attn_kernel(const float* __restrict__ logit_scale)
{
    int bh = blockIdx.x;
    int b = bh / NH, h = bh % NH;
    __shared__ float qs[NT * QKP];
    __shared__ float ks[NT * QKP];
    __shared__ float vt[HD * PSP];
    __shared__ float ps[NT * PSP];

    int tid = threadIdx.x, lane = tid & 31, warp = tid >> 5;
    float scale = __expf(fminf(logit_scale[h], LOG_MAX_SCALE));

    size_t base = (size_t)(b * NT) * QKVN + (size_t)h * HD;
    for (int idx = tid; idx < NT * 8; idx += 256) {
        int i = idx >> 3, d4 = (idx & 7) * 4;
        size_t off = base + (size_t)i * QKVN + d4;
        float4 qv = *(const float4*)(g_qkv + off);
        float4 kv = *(const float4*)(g_qkv + off + CD);
        float4 vv = *(const float4*)(g_qkv + off + 2 * CD);
        *(float4*)(qs + i * QKP + d4) = qv;
        *(float4*)(ks + i * QKP + d4) = kv;
        vt[(d4 + 0) * PSP + i] = vv.x;
        vt[(d4 + 1) * PSP + i] = vv.y;
        vt[(d4 + 2) * PSP + i] = vv.z;
        vt[(d4 + 3) * PSP + i] = vv.w;
    }
    __syncthreads();

    // l2-normalize q (fold scale) and k
    for (int i = warp; i < NT; i += 8) {
        float qv = qs[i * QKP + lane];
        float s = qv * qv;
        #pragma unroll
        for (int o = 16; o > 0; o >>= 1) s += __shfl_xor_sync(0xffffffffu, s, o);
        qs[i * QKP + lane] = qv * (scale / (sqrtf(s) + 1e-12f));
        float kv = ks[i * QKP + lane];
        float s2 = kv * kv;
        #pragma unroll
        for (int o = 16; o > 0; o >>= 1) s2 += __shfl_xor_sync(0xffffffffu, s2, o);
        ks[i * QKP + lane] = kv / (sqrtf(s2) + 1e-12f);
    }
    __syncthreads();

    // ---- score phase: 4 row-pairs per warp, K cached per quarter ----
    int j1 = (lane < 17) ? (lane + 32) : 0;
    float d00[4], d01[4], d10[4], d11[4];
    #pragma unroll
    for (int p = 0; p < 4; p++) { d00[p] = d01[p] = d10[p] = d11[p] = 0.0f; }

    #pragma unroll
    for (int q8 = 0; q8 < HD; q8 += 8) {
        float4 k0a = *(const float4*)(ks + lane * QKP + q8);
        float4 k0b = *(const float4*)(ks + lane * QKP + q8 + 4);
        float4 k1a = *(const float4*)(ks + j1 * QKP + q8);
        float4 k1b = *(const float4*)(ks + j1 * QKP + q8 + 4);
        #pragma unroll
        for (int p = 0; p < 4; p++) {
            int i0 = warp * 2 + p * 16;
            if (i0 >= NT) continue;
            int i1 = (i0 + 1 < NT) ? (i0 + 1) : i0;
            float4 q0a = *(const float4*)(qs + i0 * QKP + q8);
            float4 q0b = *(const float4*)(qs + i0 * QKP + q8 + 4);
            float4 q1a = *(const float4*)(qs + i1 * QKP + q8);
            float4 q1b = *(const float4*)(qs + i1 * QKP + q8 + 4);
            d00[p] = dot4(q0b, k0b, dot4(q0a, k0a, d00[p]));
            d01[p] = dot4(q0b, k1b, dot4(q0a, k1a, d01[p]));
            d10[p] = dot4(q1b, k0b, dot4(q1a, k0a, d10[p]));
            d11[p] = dot4(q1b, k1b, dot4(q1a, k1a, d11[p]));
        }
    }

    // ---- softmax per pair (bias read directly from L2-resident table) ----
    const float* bias_h = g_bias + h * NT * NT;
    #pragma unroll
    for (int p = 0; p < 4; p++) {
        int i0 = warp * 2 + p * 16;
        if (i0 >= NT) continue;
        bool has1 = (i0 + 1 < NT);
        {
            float s0 = d00[p] + __ldg(bias_h + i0 * NT + lane);
            float s1 = (lane < 17) ? (d01[p] + __ldg(bias_h + i0 * NT + 32 + lane)) : -INFINITY;
            float m = fmaxf(s0, s1);
            #pragma unroll
            for (int o = 16; o > 0; o >>= 1) m = fmaxf(m, __shfl_xor_sync(0xffffffffu, m, o));
            float e0 = __expf(s0 - m);
            float e1 = (lane < 17) ? __expf(s1 - m) : 0.0f;
            float sum = e0 + e1;
            #pragma unroll
            for (int o = 16; o > 0; o >>= 1) sum += __shfl_xor_sync(0xffffffffu, sum, o);
            float inv = __fdividef(1.0f, sum);
            ps[i0 * PSP + lane] = e0 * inv;
            if (lane < 17) ps[i0 * PSP + 32 + lane] = e1 * inv;
        }
        if (has1) {
            int i1 = i0 + 1;
            float s0 = d10[p] + __ldg(bias_h + i1 * NT + lane);
            float s1 = (lane < 17) ? (d11[p] + __ldg(bias_h + i1 * NT + 32 + lane)) : -INFINITY;
            float m = fmaxf(s0, s1);
            #pragma unroll
            for (int o = 16; o > 0; o >>= 1) m = fmaxf(m, __shfl_xor_sync(0xffffffffu, m, o));
            float e0 = __expf(s0 - m);
            float e1 = (lane < 17) ? __expf(s1 - m) : 0.0f;
            float sum = e0 + e1;
            #pragma unroll
            for (int o = 16; o > 0; o >>= 1) sum += __shfl_xor_sync(0xffffffffu, sum, o);
            float inv = __fdividef(1.0f, sum);
            ps[i1 * PSP + lane] = e0 * inv;
            if (lane < 17) ps[i1 * PSP + 32 + lane] = e1 * inv;
        }
    }
    __syncthreads();

    // ---- PV phase: V chunk cached in registers across all 4 pairs ----
    float a0[4], a1[4];
    #pragma unroll
    for (int p = 0; p < 4; p++) { a0[p] = a1[p] = 0.0f; }

    #pragma unroll
    for (int jc = 0; jc < 48; jc += 16) {
        float4 v0 = *(const float4*)(vt + lane * PSP + jc);
        float4 v1 = *(const float4*)(vt + lane * PSP + jc + 4);
        float4 v2 = *(const float4*)(vt + lane * PSP + jc + 8);
        float4 v3 = *(const float4*)(vt + lane * PSP + jc + 12);
        #pragma unroll
        for (int p = 0; p < 4; p++) {
            int i0 = warp * 2 + p * 16;
            if (i0 >= NT) continue;
            int i1 = (i0 + 1 < NT) ? (i0 + 1) : i0;
            float4 p00 = *(const float4*)(ps + i0 * PSP + jc);
            float4 p01 = *(const float4*)(ps + i0 * PSP + jc + 4);
            float4 p02 = *(const float4*)(ps + i0 * PSP + jc + 8);
            float4 p03 = *(const float4*)(ps + i0 * PSP + jc + 12);
            a0[p] = dot4(p03, v3, dot4(p02, v2, dot4(p01, v1, dot4(p00, v0, a0[p]))));
            float4 p10 = *(const float4*)(ps + i1 * PSP + jc);
            float4 p11 = *(const float4*)(ps + i1 * PSP + jc + 4);
            float4 p12 = *(const float4*)(ps + i1 * PSP + jc + 8);
            float4 p13 = *(const float4*)(ps + i1 * PSP + jc + 12);
            a1[p] = dot4(p13, v3, dot4(p12, v2, dot4(p11, v1, dot4(p10, v0, a1[p]))));
        }
    }
    // tail j = 48 + stores
    {
        float vv = vt[lane * PSP + 48];
        #pragma unroll
        for (int p = 0; p < 4; p++) {
            int i0 = warp * 2 + p * 16;
            if (i0 >= NT) continue;
            bool has1 = (i0 + 1 < NT);
            int i1 = has1 ? (i0 + 1) : i0;
            a0[p] = fmaf(ps[i0 * PSP + 48], vv, a0[p]);
            a1[p] = fmaf(ps[i1 * PSP + 48], vv, a1[p]);
            g_ao[(size_t)(b * NT + i0) * CD + h * HD + lane] = a0[p];
            if (has1)
                g_ao[(size_t)(b * NT + i1) * CD + h * HD + lane] = a1[p];
        }
    }
}

// ---------------------------------------------------------------------------
extern "C" void kernel_launch(void* const* d_in, const int* in_sizes, int n_in,
                              void* d_out, int out_size)
{
    const float* x           = (const float*)d_in[0];
    const float* qkv_w       = (const float*)d_in[1];
    const float* q_bias      = (const float*)d_in[2];
    const float* v_bias      = (const float*)d_in[3];
    const float* logit_scale = (const float*)d_in[4];
    const float* cpb_w1      = (const float*)d_in[5];
    const float* cpb_b1      = (const float*)d_in[6];
    const float* cpb_w2      = (const float*)d_in[7];
    const float* proj_w      = (const float*)d_in[8];
    const float* proj_b      = (const float*)d_in[9];
    float* out = (float*)d_out;

    void* p;
    cudaGetSymbolAddress(&p, g_qkv); float* qkv = (float*)p;
    cudaGetSymbolAddress(&p, g_ao);  float* ao  = (float*)p;

    cpb_mlp_kernel<<<TBL, 128>>>(cpb_w1, cpb_b1, cpb_w2);
    bias_expand_kernel<<<(NH * NT * NT + 255) / 256, 256>>>();

    dim3 gq(QKVN / 128, MROWS / 128);
    gemm_tf32<QKVN, CD, 0><<<gq, 256>>>(x, qkv_w, qkv, q_bias, v_bias);

    attn_kernel<<<BQ * NH, 256>>>(logit_scale);

    dim3 gp(CD / 128, MROWS / 128);
    gemm_tf32<CD, CD, 1><<<gp, 256>>>(ao, proj_w, out, proj_b, nullptr);
}